// round 2
// baseline (speedup 1.0000x reference)
#include <cuda_runtime.h>
#include <cuda_bf16.h>

#define N0_ 262144
#define N1_ 32768
#define N2_ 4096
#define EPS_ 1e-5f

// Static scratch (no allocation allowed)
__device__ float4 g_data4[N0_];          // padded input rows (3 -> 4 floats)
__device__ float g_y0[N0_ * 24];
__device__ float g_y1[N1_ * 48];
__device__ float g_y2[N1_ * 48];
__device__ float g_y3[N2_ * 96];
__device__ float g_y4[N2_ * 96];
__device__ float g_psum[1024 * 96];
__device__ float g_psq [1024 * 96];
__device__ float g_scale[5 * 96];
__device__ float g_shift[5 * 96];
__device__ int   g_ctrs[8];              // zero-init; each stage resets its own

// ---------------------------------------------------------------------------
// Gather-conv stage with fused BN-statistics + fused BN finalize (last block).
//   y[m, dofs+j] = sum_k sum_c act(x[neigh[m,k], c]) * W[k, c, dofs+j]
// act() = BN(scale,shift)+ReLU of the PREVIOUS stage when NORM_IN.
// One thread = one row x DTILE output channels. Weights staged in SMEM in
// K-chunks. Per-block partial sum/sumsq written to psum/psq; the last block
// (atomic counter) reduces them into scale/shift for the NEXT stage.
// ---------------------------------------------------------------------------
template<int K, int CIN, int CINS, int COUT, int DTILE, int KCHUNK, int NTH,
         bool NORM_IN, bool IDXS>
__global__ void __launch_bounds__(NTH)
conv_stage(const float* __restrict__ xin,
           const int*   __restrict__ neigh,
           const float* __restrict__ W,       // [K, CIN, COUT]
           const float* __restrict__ nscale,  // [CIN]  (NORM_IN)
           const float* __restrict__ nshift,  // [CIN]
           float* __restrict__ yout,          // [M, COUT]
           float* __restrict__ psum,          // [grid.x * COUT]
           float* __restrict__ psq,
           const float* __restrict__ gamma,   // [COUT]
           const float* __restrict__ beta,
           float* __restrict__ oscale,        // [COUT]
           float* __restrict__ oshift,
           float invM, int* __restrict__ ctr)
{
    constexpr int NCH    = K / KCHUNK;
    constexpr int CIN_LD = (CIN + 3) / 4;
    constexpr int NW     = NTH / 32;

    __shared__ float sW[KCHUNK * CIN * DTILE];
    __shared__ float sScale[NORM_IN ? CIN : 1];
    __shared__ float sShift[NORM_IN ? CIN : 1];
    __shared__ float sRed[NW][DTILE][2];
    __shared__ int   sIdx[IDXS ? NTH * K : 1];
    __shared__ int   sLast;

    const int tid  = threadIdx.x;
    const int dofs = blockIdx.y * DTILE;
    const int row  = blockIdx.x * NTH + tid;

    if (NORM_IN) {
        for (int c = tid; c < CIN; c += NTH) {
            sScale[c] = nscale[c];
            sShift[c] = nshift[c];
        }
    }
    if (IDXS) {
        const long base = (long)blockIdx.x * NTH * K;
        for (int i = tid; i < NTH * K; i += NTH) sIdx[i] = neigh[base + i];
    }

    int idx8[(K == 8) ? 8 : 1];
    if constexpr (K == 8) {
        const int4* nr = reinterpret_cast<const int4*>(neigh + (long)row * 8);
        int4 a = nr[0], b = nr[1];
        idx8[0]=a.x; idx8[1]=a.y; idx8[2]=a.z; idx8[3]=a.w;
        idx8[4]=b.x; idx8[5]=b.y; idx8[6]=b.z; idx8[7]=b.w;
    }

    float acc[DTILE];
#pragma unroll
    for (int j = 0; j < DTILE; j++) acc[j] = 0.f;

    for (int ch = 0; ch < NCH; ch++) {
        const int k0 = ch * KCHUNK;
        __syncthreads();
        for (int i = tid; i < KCHUNK * CIN * DTILE; i += NTH) {
            const int j   = i % DTILE;
            const int rem = i / DTILE;
            const int c   = rem % CIN;
            const int k   = rem / CIN;
            sW[i] = W[((long)(k0 + k) * CIN + c) * COUT + dofs + j];
        }
        __syncthreads();

        int idxs[KCHUNK];
#pragma unroll
        for (int kk = 0; kk < KCHUNK; kk++) {
            if constexpr (K == 8)      idxs[kk] = idx8[k0 + kk];
            else if constexpr (IDXS)   idxs[kk] = sIdx[tid * K + k0 + kk];
            else                       idxs[kk] = neigh[(long)row * K + k0 + kk];
        }

#pragma unroll
        for (int kk = 0; kk < KCHUNK; kk++) {
            const float4* __restrict__ xr4 =
                reinterpret_cast<const float4*>(xin + (long)idxs[kk] * CINS);
            const float* __restrict__ wr = &sW[kk * CIN * DTILE];
#pragma unroll
            for (int q = 0; q < CIN_LD; q++) {
                float4 xv = xr4[q];
                float v[4] = {xv.x, xv.y, xv.z, xv.w};
#pragma unroll
                for (int u = 0; u < 4; u++) {
                    const int c = q * 4 + u;
                    if (c >= CIN) break;
                    float x = v[u];
                    if (NORM_IN) x = fmaxf(fmaf(x, sScale[c], sShift[c]), 0.f);
                    const float* wrow = wr + c * DTILE;
#pragma unroll
                    for (int j = 0; j < DTILE; j += 4) {
                        float4 w4 = *reinterpret_cast<const float4*>(wrow + j);
                        acc[j+0] = fmaf(x, w4.x, acc[j+0]);
                        acc[j+1] = fmaf(x, w4.y, acc[j+1]);
                        acc[j+2] = fmaf(x, w4.z, acc[j+2]);
                        acc[j+3] = fmaf(x, w4.w, acc[j+3]);
                    }
                }
            }
        }
    }

    // Store raw outputs (vectorized; dofs*4B and COUT*4B are 16B multiples)
#pragma unroll
    for (int j = 0; j < DTILE; j += 4) {
        *reinterpret_cast<float4*>(&yout[(long)row * COUT + dofs + j]) =
            make_float4(acc[j], acc[j+1], acc[j+2], acc[j+3]);
    }

    // Deterministic block partials
    const int lane = tid & 31;
    const int warp = tid >> 5;
#pragma unroll
    for (int j = 0; j < DTILE; j++) {
        float s = acc[j];
        float q = acc[j] * acc[j];
#pragma unroll
        for (int off = 16; off > 0; off >>= 1) {
            s += __shfl_down_sync(0xFFFFFFFFu, s, off);
            q += __shfl_down_sync(0xFFFFFFFFu, q, off);
        }
        if (lane == 0) { sRed[warp][j][0] = s; sRed[warp][j][1] = q; }
    }
    __syncthreads();
    if (tid < DTILE) {
        float s = 0.f, q = 0.f;
#pragma unroll
        for (int w = 0; w < NW; w++) { s += sRed[w][tid][0]; q += sRed[w][tid][1]; }
        psum[(long)blockIdx.x * COUT + dofs + tid] = s;
        psq [(long)blockIdx.x * COUT + dofs + tid] = q;
    }

    // Fused BN finalize: last block reduces all partials -> scale/shift
    __threadfence();
    __syncthreads();
    if (tid == 0) {
        int old = atomicAdd(ctr, 1);
        sLast = (old == (int)(gridDim.x * gridDim.y) - 1);
    }
    __syncthreads();
    if (sLast) {
        __threadfence();
        const int nRB = gridDim.x;
        for (int d = warp; d < COUT; d += NW) {
            float s = 0.f, q = 0.f;
            for (int b = lane; b < nRB; b += 32) {
                s += psum[(long)b * COUT + d];
                q += psq [(long)b * COUT + d];
            }
#pragma unroll
            for (int off = 16; off > 0; off >>= 1) {
                s += __shfl_down_sync(0xFFFFFFFFu, s, off);
                q += __shfl_down_sync(0xFFFFFFFFu, q, off);
            }
            if (lane == 0) {
                const float mean = s * invM;
                const float var  = q * invM - mean * mean;
                const float sc   = gamma[d] * rsqrtf(var + EPS_);
                oscale[d] = sc;
                oshift[d] = beta[d] - mean * sc;
            }
        }
        __syncthreads();
        if (tid == 0) *ctr = 0;
    }
}

// Pad data rows 3 -> 4 floats so gathers are single LDG.128
__global__ void pad4_kernel(const float* __restrict__ d, float4* __restrict__ o)
{
    const int i = blockIdx.x * 256 + threadIdx.x;
    if (i < N0_)
        o[i] = make_float4(d[3*i], d[3*i+1], d[3*i+2], 0.f);
}

// Final elementwise BN + ReLU into d_out
__global__ void final_norm(const float* __restrict__ y,
                           const float* __restrict__ scale,
                           const float* __restrict__ shift,
                           float* __restrict__ out, int total, int cout)
{
    const int i = blockIdx.x * 256 + threadIdx.x;
    if (i < total) {
        const int d = i % cout;
        out[i] = fmaxf(fmaf(y[i], scale[d], shift[d]), 0.f);
    }
}

// ---------------------------------------------------------------------------
extern "C" void kernel_launch(void* const* d_in, const int* in_sizes, int n_in,
                              void* d_out, int out_size)
{
    const float* data   = (const float*)d_in[0];
    const int*   neigh0 = (const int*)  d_in[1];
    const int*   child0 = (const int*)  d_in[2];
    const int*   neigh1 = (const int*)  d_in[3];
    const int*   child1 = (const int*)  d_in[4];
    const int*   neigh2 = (const int*)  d_in[5];
    const float* w0  = (const float*)d_in[6];
    const float* g0  = (const float*)d_in[7];
    const float* b0  = (const float*)d_in[8];
    const float* wd0 = (const float*)d_in[9];
    const float* gd0 = (const float*)d_in[10];
    const float* bd0 = (const float*)d_in[11];
    const float* w1  = (const float*)d_in[12];
    const float* g1  = (const float*)d_in[13];
    const float* b1  = (const float*)d_in[14];
    const float* wd1 = (const float*)d_in[15];
    const float* gd1 = (const float*)d_in[16];
    const float* bd1 = (const float*)d_in[17];
    const float* wp  = (const float*)d_in[18];
    const float* gp  = (const float*)d_in[19];
    const float* bp  = (const float*)d_in[20];

    float4 *x4; float *y0,*y1,*y2,*y3,*y4,*psum,*psq,*scl,*shf; int *ctrs;
    cudaGetSymbolAddress((void**)&x4,   g_data4);
    cudaGetSymbolAddress((void**)&y0,   g_y0);
    cudaGetSymbolAddress((void**)&y1,   g_y1);
    cudaGetSymbolAddress((void**)&y2,   g_y2);
    cudaGetSymbolAddress((void**)&y3,   g_y3);
    cudaGetSymbolAddress((void**)&y4,   g_y4);
    cudaGetSymbolAddress((void**)&psum, g_psum);
    cudaGetSymbolAddress((void**)&psq,  g_psq);
    cudaGetSymbolAddress((void**)&scl,  g_scale);
    cudaGetSymbolAddress((void**)&shf,  g_shift);
    cudaGetSymbolAddress((void**)&ctrs, g_ctrs);

    // launch 0: pad input rows to float4
    pad4_kernel<<<(N0_ + 255) / 256, 256>>>(data, x4);

    // launch 1 — Stage A: data4 x w0[27,3,24] -> y0 raw + BN0 scale/shift
    conv_stage<27, 3, 4, 24, 24, 27, 256, false, true>
        <<<dim3(N0_/256, 1), 256>>>(
        (const float*)x4, neigh0, w0, nullptr, nullptr, y0, psum, psq,
        g0, b0, scl + 0, shf + 0, 1.f / N0_, ctrs + 0);

    // launch 2 — Stage B: norm0(y0) x wd0[8,24,48] -> y1 raw + BN1
    conv_stage<8, 24, 24, 48, 24, 4, 128, true, false>
        <<<dim3(N1_/128, 2), 128>>>(
        y0, child0, wd0, scl + 0, shf + 0, y1, psum, psq,
        gd0, bd0, scl + 96, shf + 96, 1.f / N1_, ctrs + 1);

    // launch 3 — Stage C: norm1(y1) x w1[27,48,48] -> y2 raw + BN2
    conv_stage<27, 48, 48, 48, 24, 3, 128, true, true>
        <<<dim3(N1_/128, 2), 128>>>(
        y1, neigh1, w1, scl + 96, shf + 96, y2, psum, psq,
        g1, b1, scl + 192, shf + 192, 1.f / N1_, ctrs + 2);

    // launch 4 — Stage D: norm2(y2) x wd1[8,48,96] -> y3 raw + BN3
    conv_stage<8, 48, 48, 96, 12, 4, 128, true, false>
        <<<dim3(N2_/128, 8), 128>>>(
        y2, child1, wd1, scl + 192, shf + 192, y3, psum, psq,
        gd1, bd1, scl + 288, shf + 288, 1.f / N2_, ctrs + 3);

    // launch 5 — Stage E: norm3(y3) x wp[27,96,96] -> y4 raw + BN4  (ncu target)
    conv_stage<27, 96, 96, 96, 8, 3, 128, true, true>
        <<<dim3(N2_/128, 12), 128>>>(
        y3, neigh2, wp, scl + 288, shf + 288, y4, psum, psq,
        gp, bp, scl + 384, shf + 384, 1.f / N2_, ctrs + 4);

    // launch 6 — final BN + ReLU -> d_out [N2, 96]
    final_norm<<<(N2_ * 96 + 255) / 256, 256>>>(
        y4, scl + 384, shf + 384, (float*)d_out, N2_ * 96, 96);
}

// round 3
// speedup vs baseline: 1.1775x; 1.1775x over previous
#include <cuda_runtime.h>
#include <cuda_bf16.h>

#define N0_ 262144
#define N1_ 32768
#define N2_ 4096
#define EPS_ 1e-5f

// Static scratch
__device__ float4 g_data4[N0_];
__device__ float g_y0[N0_ * 24];
__device__ float g_y1[N1_ * 48];
__device__ float g_y2[N1_ * 48];
__device__ float g_y3[N2_ * 96];
__device__ float g_y4[N2_ * 96];
__device__ float g_psum[1024 * 96];
__device__ float g_psq [1024 * 96];
__device__ float g_scale[5 * 96];
__device__ float g_shift[5 * 96];
__device__ int   g_ctrs[8];

// ---------------------------------------------------------------------------
// SMEM-tiled gather-GEMM stage (stages B..E).
// Per k: gather MTILE rows (CIN floats, coalesced 16B chunks, norm applied)
// into sX[CIN][MTILE] (transposed), stage W[k][:, dofs:dofs+NTILE] into
// sW[CIN][NTILE], then register-tiled GEMM MR x NR per thread.
// Fused BN stats + last-block finalize producing next stage's scale/shift.
// ---------------------------------------------------------------------------
template<int K, int CIN, int COUT, int NTILE, int MTILE, int MR, int NR,
         int NTH, bool NORM_IN>
__global__ void __launch_bounds__(NTH)
conv_gemm(const float* __restrict__ xin,
          const int*   __restrict__ neigh,
          const float* __restrict__ W,       // [K, CIN, COUT]
          const float* __restrict__ nscale,
          const float* __restrict__ nshift,
          float* __restrict__ yout,          // [M, COUT]
          float* __restrict__ psum,
          float* __restrict__ psq,
          const float* __restrict__ gamma,
          const float* __restrict__ beta,
          float* __restrict__ oscale,
          float* __restrict__ oshift,
          float invM, int* __restrict__ ctr)
{
    constexpr int NCG = NTILE / NR;     // channel groups
    constexpr int NRG = MTILE / MR;     // row groups
    static_assert(NTH == NCG * NRG, "thread layout");
    constexpr int KP = (K % 2) ? K : (K + 1);   // padded idx stride
    constexpr int NW = NTH / 32;

    __shared__ float sX[CIN][MTILE];
    __shared__ float sW[CIN][NTILE];
    __shared__ float sScale[NORM_IN ? CIN : 1];
    __shared__ float sShift[NORM_IN ? CIN : 1];
    __shared__ int   sIdx[MTILE * KP];
    __shared__ float sRed[NRG][NTILE][2];
    __shared__ int   sLast;

    const int tid  = threadIdx.x;
    const int cg   = tid % NCG;
    const int rg   = tid / NCG;
    const int r0   = rg * MR;
    const int c0   = cg * NR;
    const int dofs = blockIdx.y * NTILE;
    const int rowbase = blockIdx.x * MTILE;

    if (NORM_IN) {
        for (int c = tid; c < CIN; c += NTH) {
            sScale[c] = nscale[c];
            sShift[c] = nshift[c];
        }
    }
    // Stage all neighbor indices for this block (coalesced)
    for (int i = tid; i < MTILE * K; i += NTH) {
        const int r = i / K, k = i % K;
        sIdx[r * KP + k] = neigh[(long)rowbase * K + i];
    }

    float acc[MR][NR];
#pragma unroll
    for (int m = 0; m < MR; m++)
#pragma unroll
        for (int j = 0; j < NR; j++) acc[m][j] = 0.f;

    for (int k = 0; k < K; k++) {
        __syncthreads();   // prev c-loop done; also covers sIdx/sScale on k==0
        // W[k] slice -> sW (coalesced)
        for (int i = tid; i < CIN * (NTILE / 4); i += NTH) {
            const int c = i / (NTILE / 4);
            const int j = (i % (NTILE / 4)) * 4;
            float4 w = *reinterpret_cast<const float4*>(
                &W[((long)k * CIN + c) * COUT + dofs + j]);
            *reinterpret_cast<float4*>(&sW[c][j]) = w;
        }
        // Gather X tile (lanes: consecutive rows, same 16B chunk)
        for (int i = tid; i < MTILE * (CIN / 4); i += NTH) {
            const int r = i % MTILE;
            const int q = i / MTILE;
            const int idx = sIdx[r * KP + k];
            float4 xv = *reinterpret_cast<const float4*>(
                xin + (long)idx * CIN + q * 4);
            if (NORM_IN) {
                xv.x = fmaxf(fmaf(xv.x, sScale[q*4+0], sShift[q*4+0]), 0.f);
                xv.y = fmaxf(fmaf(xv.y, sScale[q*4+1], sShift[q*4+1]), 0.f);
                xv.z = fmaxf(fmaf(xv.z, sScale[q*4+2], sShift[q*4+2]), 0.f);
                xv.w = fmaxf(fmaf(xv.w, sScale[q*4+3], sShift[q*4+3]), 0.f);
            }
            sX[q*4+0][r] = xv.x;
            sX[q*4+1][r] = xv.y;
            sX[q*4+2][r] = xv.z;
            sX[q*4+3][r] = xv.w;
        }
        __syncthreads();

#pragma unroll 4
        for (int c = 0; c < CIN; c++) {
            float4 w4 = *reinterpret_cast<const float4*>(&sW[c][c0]);
            const float wv[4] = {w4.x, w4.y, w4.z, w4.w};
#pragma unroll
            for (int m4 = 0; m4 < MR / 4; m4++) {
                float4 a = *reinterpret_cast<const float4*>(&sX[c][r0 + m4*4]);
                const float av[4] = {a.x, a.y, a.z, a.w};
#pragma unroll
                for (int u = 0; u < 4; u++)
#pragma unroll
                    for (int j = 0; j < NR; j++)
                        acc[m4*4+u][j] = fmaf(av[u], wv[j], acc[m4*4+u][j]);
            }
        }
    }

    // Store raw outputs (NR==4 -> float4)
#pragma unroll
    for (int m = 0; m < MR; m++) {
        const long row = rowbase + r0 + m;
        *reinterpret_cast<float4*>(&yout[row * COUT + dofs + c0]) =
            make_float4(acc[m][0], acc[m][1], acc[m][2], acc[m][3]);
    }

    // Per-thread channel partials -> sRed[rg][channel]
#pragma unroll
    for (int j = 0; j < NR; j++) {
        float s = 0.f, q = 0.f;
#pragma unroll
        for (int m = 0; m < MR; m++) {
            s += acc[m][j];
            q += acc[m][j] * acc[m][j];
        }
        sRed[rg][c0 + j][0] = s;
        sRed[rg][c0 + j][1] = q;
    }
    __syncthreads();
    if (tid < NTILE) {
        float s = 0.f, q = 0.f;
#pragma unroll
        for (int g = 0; g < NRG; g++) {
            s += sRed[g][tid][0];
            q += sRed[g][tid][1];
        }
        psum[(long)blockIdx.x * COUT + dofs + tid] = s;
        psq [(long)blockIdx.x * COUT + dofs + tid] = q;
    }

    // Last block: global BN finalize
    __threadfence();
    __syncthreads();
    if (tid == 0) {
        int old = atomicAdd(ctr, 1);
        sLast = (old == (int)(gridDim.x * gridDim.y) - 1);
    }
    __syncthreads();
    if (sLast) {
        __threadfence();
        const int lane = tid & 31, warp = tid >> 5;
        const int nRB = gridDim.x;
        for (int d = warp; d < COUT; d += NW) {
            float s = 0.f, q = 0.f;
            for (int b = lane; b < nRB; b += 32) {
                s += psum[(long)b * COUT + d];
                q += psq [(long)b * COUT + d];
            }
#pragma unroll
            for (int off = 16; off > 0; off >>= 1) {
                s += __shfl_down_sync(0xFFFFFFFFu, s, off);
                q += __shfl_down_sync(0xFFFFFFFFu, q, off);
            }
            if (lane == 0) {
                const float mean = s * invM;
                const float var  = q * invM - mean * mean;
                const float sc   = gamma[d] * rsqrtf(var + EPS_);
                oscale[d] = sc;
                oshift[d] = beta[d] - mean * sc;
            }
        }
        __syncthreads();
        if (tid == 0) *ctr = 0;
    }
}

// ---------------------------------------------------------------------------
// Stage A: CIN=3 (padded to 4), one thread per row, full weights in SMEM
// (all W LDS are warp-uniform broadcasts). Fused stats + finalize.
// ---------------------------------------------------------------------------
__global__ void __launch_bounds__(256)
conv_stageA(const float4* __restrict__ x4,
            const int*   __restrict__ neigh,   // [N0, 27]
            const float* __restrict__ W,       // [27, 3, 24]
            float* __restrict__ yout,          // [N0, 24]
            float* __restrict__ psum, float* __restrict__ psq,
            const float* __restrict__ gamma, const float* __restrict__ beta,
            float* __restrict__ oscale, float* __restrict__ oshift,
            float invM, int* __restrict__ ctr)
{
    __shared__ float sW[27 * 3 * 24];
    __shared__ int   sIdx[256 * 27];
    __shared__ float sRed[8][24][2];
    __shared__ int   sLast;

    const int tid = threadIdx.x;
    const int row = blockIdx.x * 256 + tid;

    for (int i = tid; i < 27 * 3 * 24; i += 256) sW[i] = W[i];
    {
        const long base = (long)blockIdx.x * 256 * 27;
        for (int i = tid; i < 256 * 27; i += 256) sIdx[i] = neigh[base + i];
    }
    __syncthreads();

    float acc[24];
#pragma unroll
    for (int j = 0; j < 24; j++) acc[j] = 0.f;

#pragma unroll 3
    for (int k = 0; k < 27; k++) {
        const int idx = sIdx[tid * 27 + k];
        float4 xv = x4[idx];
        const float v[3] = {xv.x, xv.y, xv.z};
#pragma unroll
        for (int c = 0; c < 3; c++) {
            const float* wrow = &sW[(k * 3 + c) * 24];
#pragma unroll
            for (int j = 0; j < 24; j += 4) {
                float4 w4 = *reinterpret_cast<const float4*>(wrow + j);
                acc[j+0] = fmaf(v[c], w4.x, acc[j+0]);
                acc[j+1] = fmaf(v[c], w4.y, acc[j+1]);
                acc[j+2] = fmaf(v[c], w4.z, acc[j+2]);
                acc[j+3] = fmaf(v[c], w4.w, acc[j+3]);
            }
        }
    }

#pragma unroll
    for (int j = 0; j < 24; j += 4)
        *reinterpret_cast<float4*>(&yout[(long)row * 24 + j]) =
            make_float4(acc[j], acc[j+1], acc[j+2], acc[j+3]);

    const int lane = tid & 31, warp = tid >> 5;
#pragma unroll
    for (int j = 0; j < 24; j++) {
        float s = acc[j];
        float q = acc[j] * acc[j];
#pragma unroll
        for (int off = 16; off > 0; off >>= 1) {
            s += __shfl_down_sync(0xFFFFFFFFu, s, off);
            q += __shfl_down_sync(0xFFFFFFFFu, q, off);
        }
        if (lane == 0) { sRed[warp][j][0] = s; sRed[warp][j][1] = q; }
    }
    __syncthreads();
    if (tid < 24) {
        float s = 0.f, q = 0.f;
#pragma unroll
        for (int w = 0; w < 8; w++) { s += sRed[w][tid][0]; q += sRed[w][tid][1]; }
        psum[(long)blockIdx.x * 24 + tid] = s;
        psq [(long)blockIdx.x * 24 + tid] = q;
    }

    __threadfence();
    __syncthreads();
    if (tid == 0) {
        int old = atomicAdd(ctr, 1);
        sLast = (old == (int)gridDim.x - 1);
    }
    __syncthreads();
    if (sLast) {
        __threadfence();
        const int nRB = gridDim.x;
        for (int d = warp; d < 24; d += 8) {
            float s = 0.f, q = 0.f;
            for (int b = lane; b < nRB; b += 32) {
                s += psum[(long)b * 24 + d];
                q += psq [(long)b * 24 + d];
            }
#pragma unroll
            for (int off = 16; off > 0; off >>= 1) {
                s += __shfl_down_sync(0xFFFFFFFFu, s, off);
                q += __shfl_down_sync(0xFFFFFFFFu, q, off);
            }
            if (lane == 0) {
                const float mean = s * invM;
                const float var  = q * invM - mean * mean;
                const float sc   = gamma[d] * rsqrtf(var + EPS_);
                oscale[d] = sc;
                oshift[d] = beta[d] - mean * sc;
            }
        }
        __syncthreads();
        if (tid == 0) *ctr = 0;
    }
}

__global__ void pad4_kernel(const float* __restrict__ d, float4* __restrict__ o)
{
    const int i = blockIdx.x * 256 + threadIdx.x;
    if (i < N0_)
        o[i] = make_float4(d[3*i], d[3*i+1], d[3*i+2], 0.f);
}

__global__ void final_norm(const float* __restrict__ y,
                           const float* __restrict__ scale,
                           const float* __restrict__ shift,
                           float* __restrict__ out, int total, int cout)
{
    const int i = blockIdx.x * 256 + threadIdx.x;
    if (i < total) {
        const int d = i % cout;
        out[i] = fmaxf(fmaf(y[i], scale[d], shift[d]), 0.f);
    }
}

// ---------------------------------------------------------------------------
extern "C" void kernel_launch(void* const* d_in, const int* in_sizes, int n_in,
                              void* d_out, int out_size)
{
    const float* data   = (const float*)d_in[0];
    const int*   neigh0 = (const int*)  d_in[1];
    const int*   child0 = (const int*)  d_in[2];
    const int*   neigh1 = (const int*)  d_in[3];
    const int*   child1 = (const int*)  d_in[4];
    const int*   neigh2 = (const int*)  d_in[5];
    const float* w0  = (const float*)d_in[6];
    const float* g0  = (const float*)d_in[7];
    const float* b0  = (const float*)d_in[8];
    const float* wd0 = (const float*)d_in[9];
    const float* gd0 = (const float*)d_in[10];
    const float* bd0 = (const float*)d_in[11];
    const float* w1  = (const float*)d_in[12];
    const float* g1  = (const float*)d_in[13];
    const float* b1  = (const float*)d_in[14];
    const float* wd1 = (const float*)d_in[15];
    const float* gd1 = (const float*)d_in[16];
    const float* bd1 = (const float*)d_in[17];
    const float* wp  = (const float*)d_in[18];
    const float* gp  = (const float*)d_in[19];
    const float* bp  = (const float*)d_in[20];

    float4 *x4; float *y0,*y1,*y2,*y3,*y4,*psum,*psq,*scl,*shf; int *ctrs;
    cudaGetSymbolAddress((void**)&x4,   g_data4);
    cudaGetSymbolAddress((void**)&y0,   g_y0);
    cudaGetSymbolAddress((void**)&y1,   g_y1);
    cudaGetSymbolAddress((void**)&y2,   g_y2);
    cudaGetSymbolAddress((void**)&y3,   g_y3);
    cudaGetSymbolAddress((void**)&y4,   g_y4);
    cudaGetSymbolAddress((void**)&psum, g_psum);
    cudaGetSymbolAddress((void**)&psq,  g_psq);
    cudaGetSymbolAddress((void**)&scl,  g_scale);
    cudaGetSymbolAddress((void**)&shf,  g_shift);
    cudaGetSymbolAddress((void**)&ctrs, g_ctrs);

    // 0: pad input rows to float4
    pad4_kernel<<<(N0_ + 255) / 256, 256>>>(data, x4);

    // 1 — Stage A: data4 x w0[27,3,24] -> y0 + BN0
    conv_stageA<<<N0_/256, 256>>>(x4, neigh0, w0, y0, psum, psq,
                                  g0, b0, scl, shf, 1.f / N0_, ctrs + 0);

    // 2 — Stage B: norm0(y0) x wd0[8,24,48] -> y1 + BN1
    conv_gemm<8, 24, 48, 48, 64, 4, 4, 192, true>
        <<<dim3(N1_/64, 1), 192>>>(
        y0, child0, wd0, scl, shf, y1, psum, psq,
        gd0, bd0, scl + 96, shf + 96, 1.f / N1_, ctrs + 1);

    // 3 — Stage C: norm1(y1) x w1[27,48,48] -> y2 + BN2
    conv_gemm<27, 48, 48, 48, 64, 8, 4, 96, true>
        <<<dim3(N1_/64, 1), 96>>>(
        y1, neigh1, w1, scl + 96, shf + 96, y2, psum, psq,
        g1, b1, scl + 192, shf + 192, 1.f / N1_, ctrs + 2);

    // 4 — Stage D: norm2(y2) x wd1[8,48,96] -> y3 + BN3
    conv_gemm<8, 48, 96, 48, 32, 4, 4, 96, true>
        <<<dim3(N2_/32, 2), 96>>>(
        y2, child1, wd1, scl + 192, shf + 192, y3, psum, psq,
        gd1, bd1, scl + 288, shf + 288, 1.f / N2_, ctrs + 3);

    // 5 — Stage E: norm3(y3) x wp[27,96,96] -> y4 + BN4  (ncu target)
    conv_gemm<27, 96, 96, 48, 32, 4, 4, 96, true>
        <<<dim3(N2_/32, 2), 96>>>(
        y3, neigh2, wp, scl + 288, shf + 288, y4, psum, psq,
        gp, bp, scl + 384, shf + 384, 1.f / N2_, ctrs + 4);

    // 6 — final BN + ReLU -> d_out [N2, 96]
    final_norm<<<(N2_ * 96 + 255) / 256, 256>>>(
        y4, scl + 384, shf + 384, (float*)d_out, N2_ * 96, 96);
}

// round 4
// speedup vs baseline: 1.3021x; 1.1058x over previous
#include <cuda_runtime.h>
#include <cuda_bf16.h>

#define N0_ 262144
#define N1_ 32768
#define N2_ 4096
#define EPS_ 1e-5f

// Static scratch
__device__ float4 g_data4[N0_];
__device__ float g_y0[N0_ * 24];
__device__ float g_y1[N1_ * 48];
__device__ float g_y2[N1_ * 48];
__device__ float g_y3[N2_ * 96];
__device__ float g_y4[N2_ * 96];
__device__ float g_ye[3][N2_ * 96];      // stage-E k-split partials
__device__ float g_psum[1024 * 96];
__device__ float g_psq [1024 * 96];
__device__ float g_scale[5 * 96];
__device__ float g_shift[5 * 96];
__device__ int   g_ctrs[8];

// ---------------------------------------------------------------------------
// Software-pipelined SMEM-tiled gather-GEMM.
// Each k: X tile (MTILE rows x CIN, normed) and W[k] slice live in SMEM;
// k+1's data is prefetched into registers during the compute of k.
// Thread layout: NCG = NTILE/4 channel groups x NRG = MTILE/MR row groups.
// Gather layout: thread always owns row slot (tid % MTILE), q-chunks strided.
// Optional fused BN stats + last-block finalize (STATS).
// K may be a slice of KSTR taps (k-split via blockIdx.z).
// ---------------------------------------------------------------------------
template<int K, int KSTR, int CIN, int COUT, int NTILE, int MTILE, int MR,
         int NTH, bool NORM_IN, bool STATS>
__global__ void __launch_bounds__(NTH)
conv_gemm(const float* __restrict__ xin,
          const int*   __restrict__ neigh,   // [M, KSTR]
          const float* __restrict__ W,       // [KSTR, CIN, COUT]
          const float* __restrict__ nscale,
          const float* __restrict__ nshift,
          float* __restrict__ yout,
          float* __restrict__ psum,
          float* __restrict__ psq,
          const float* __restrict__ gamma,
          const float* __restrict__ beta,
          float* __restrict__ oscale,
          float* __restrict__ oshift,
          float invM, int* __restrict__ ctr)
{
    constexpr int NR  = 4;
    constexpr int NCG = NTILE / NR;
    constexpr int NRG = MTILE / MR;
    static_assert(NTH == NCG * NRG, "thread layout");
    static_assert(NTH % MTILE == 0, "gather layout");
    constexpr int KP    = K + 1;
    constexpr int GIT   = (MTILE * (CIN / 4)) / NTH;
    static_assert(GIT * NTH == MTILE * (CIN / 4), "gather divisibility");
    constexpr int QSTEP = NTH / MTILE;
    constexpr int WTOT  = CIN * (NTILE / 4);
    constexpr int WIT   = (WTOT + NTH - 1) / NTH;
    constexpr bool WEXACT = (WIT * NTH == WTOT);
    constexpr int NW    = NTH / 32;

    __shared__ float sX[CIN][MTILE];
    __shared__ float sW[CIN][NTILE];
    __shared__ float sScale[NORM_IN ? CIN : 1];
    __shared__ float sShift[NORM_IN ? CIN : 1];
    __shared__ int   sIdx[MTILE * KP];
    __shared__ float sRed[STATS ? NRG : 1][STATS ? NTILE : 1][2];
    __shared__ int   sLast;

    const int tid  = threadIdx.x;
    const int cg   = tid % NCG;
    const int rg   = tid / NCG;
    const int c0   = cg * NR;
    const int r0   = rg * MR;
    const int dofs = blockIdx.y * NTILE;
    const int rowbase = blockIdx.x * MTILE;
    const int kofs = blockIdx.z * K;
    float* __restrict__ youtz =
        yout + (long)blockIdx.z * ((long)gridDim.x * MTILE) * COUT;

    if (NORM_IN) {
        for (int c = tid; c < CIN; c += NTH) {
            sScale[c] = nscale[c];
            sShift[c] = nshift[c];
        }
    }
    for (int i = tid; i < MTILE * K; i += NTH) {
        const int r = i / K, k = i % K;
        sIdx[r * KP + k] = neigh[(long)(rowbase + r) * KSTR + kofs + k];
    }
    __syncthreads();

    const int gr  = tid % MTILE;
    const int gq0 = tid / MTILE;

    float4 gx[GIT];
    float4 gw[WIT];

    auto issue = [&](int k) {
        const int idx = sIdx[gr * KP + k];
        const float4* __restrict__ xr =
            reinterpret_cast<const float4*>(xin + (long)idx * CIN);
#pragma unroll
        for (int i = 0; i < GIT; i++) gx[i] = xr[gq0 + QSTEP * i];
#pragma unroll
        for (int i = 0; i < WIT; i++) {
            const int it = tid + NTH * i;
            if (WEXACT || it < WTOT) {
                const int c  = it / (NTILE / 4);
                const int j4 = it % (NTILE / 4);
                gw[i] = *reinterpret_cast<const float4*>(
                    &W[((long)(kofs + k) * CIN + c) * COUT + dofs + j4 * 4]);
            }
        }
    };
    auto store = [&]() {
#pragma unroll
        for (int i = 0; i < GIT; i++) {
            const int q = gq0 + QSTEP * i;
            float4 xv = gx[i];
            if (NORM_IN) {
                xv.x = fmaxf(fmaf(xv.x, sScale[q*4+0], sShift[q*4+0]), 0.f);
                xv.y = fmaxf(fmaf(xv.y, sScale[q*4+1], sShift[q*4+1]), 0.f);
                xv.z = fmaxf(fmaf(xv.z, sScale[q*4+2], sShift[q*4+2]), 0.f);
                xv.w = fmaxf(fmaf(xv.w, sScale[q*4+3], sShift[q*4+3]), 0.f);
            }
            sX[q*4+0][gr] = xv.x;
            sX[q*4+1][gr] = xv.y;
            sX[q*4+2][gr] = xv.z;
            sX[q*4+3][gr] = xv.w;
        }
#pragma unroll
        for (int i = 0; i < WIT; i++) {
            const int it = tid + NTH * i;
            if (WEXACT || it < WTOT) {
                const int c  = it / (NTILE / 4);
                const int j4 = it % (NTILE / 4);
                *reinterpret_cast<float4*>(&sW[c][j4 * 4]) = gw[i];
            }
        }
    };

    float acc[MR][NR];
#pragma unroll
    for (int m = 0; m < MR; m++)
#pragma unroll
        for (int j = 0; j < NR; j++) acc[m][j] = 0.f;

    issue(0);
    store();
    __syncthreads();

    for (int k = 0; k < K; k++) {
        if (k + 1 < K) issue(k + 1);
#pragma unroll 8
        for (int c = 0; c < CIN; c++) {
            float4 w4 = *reinterpret_cast<const float4*>(&sW[c][c0]);
            const float wv[4] = {w4.x, w4.y, w4.z, w4.w};
            float xv[MR];
            if constexpr (MR == 4) {
                float4 a = *reinterpret_cast<const float4*>(&sX[c][r0]);
                xv[0] = a.x; xv[1] = a.y; xv[2] = a.z; xv[3] = a.w;
            } else {
                float2 a = *reinterpret_cast<const float2*>(&sX[c][r0]);
                xv[0] = a.x; xv[1] = a.y;
            }
#pragma unroll
            for (int m = 0; m < MR; m++)
#pragma unroll
                for (int j = 0; j < NR; j++)
                    acc[m][j] = fmaf(xv[m], wv[j], acc[m][j]);
        }
        if (k + 1 < K) {
            __syncthreads();
            store();
            __syncthreads();
        }
    }

    // Store raw outputs
#pragma unroll
    for (int m = 0; m < MR; m++) {
        const long row = rowbase + r0 + m;
        *reinterpret_cast<float4*>(&youtz[row * COUT + dofs + c0]) =
            make_float4(acc[m][0], acc[m][1], acc[m][2], acc[m][3]);
    }

    if constexpr (STATS) {
#pragma unroll
        for (int j = 0; j < NR; j++) {
            float s = 0.f, q = 0.f;
#pragma unroll
            for (int m = 0; m < MR; m++) {
                s += acc[m][j];
                q += acc[m][j] * acc[m][j];
            }
            sRed[rg][c0 + j][0] = s;
            sRed[rg][c0 + j][1] = q;
        }
        __syncthreads();
        if (tid < NTILE) {
            float s = 0.f, q = 0.f;
#pragma unroll
            for (int g = 0; g < NRG; g++) {
                s += sRed[g][tid][0];
                q += sRed[g][tid][1];
            }
            psum[(long)blockIdx.x * COUT + dofs + tid] = s;
            psq [(long)blockIdx.x * COUT + dofs + tid] = q;
        }

        __threadfence();
        __syncthreads();
        if (tid == 0) {
            int old = atomicAdd(ctr, 1);
            sLast = (old == (int)(gridDim.x * gridDim.y) - 1);
        }
        __syncthreads();
        if (sLast) {
            __threadfence();
            const int lane = tid & 31, warp = tid >> 5;
            const int nRB = gridDim.x;
            for (int d = warp; d < COUT; d += NW) {
                float s = 0.f, q = 0.f;
                for (int b = lane; b < nRB; b += 32) {
                    s += psum[(long)b * COUT + d];
                    q += psq [(long)b * COUT + d];
                }
#pragma unroll
                for (int off = 16; off > 0; off >>= 1) {
                    s += __shfl_down_sync(0xFFFFFFFFu, s, off);
                    q += __shfl_down_sync(0xFFFFFFFFu, q, off);
                }
                if (lane == 0) {
                    const float mean = s * invM;
                    const float var  = q * invM - mean * mean;
                    const float sc   = gamma[d] * rsqrtf(var + EPS_);
                    oscale[d] = sc;
                    oshift[d] = beta[d] - mean * sc;
                }
            }
            __syncthreads();
            if (tid == 0) *ctr = 0;
        }
    }
}

// ---------------------------------------------------------------------------
// Stage E combine: y4 = p0+p1+p2, fused BN stats + last-block finalize.
// 96 threads (thread = channel), 64 rows per block -> deterministic.
// ---------------------------------------------------------------------------
__global__ void __launch_bounds__(96)
combineE(const float* __restrict__ p0, const float* __restrict__ p1,
         const float* __restrict__ p2, float* __restrict__ y4,
         float* __restrict__ psum, float* __restrict__ psq,
         const float* __restrict__ gamma, const float* __restrict__ beta,
         float* __restrict__ oscale, float* __restrict__ oshift,
         float invM, int* __restrict__ ctr)
{
    __shared__ int sLast;
    const int c = threadIdx.x;
    const int rbase = blockIdx.x * 64;
    float s = 0.f, q = 0.f;
    for (int r = rbase; r < rbase + 64; r++) {
        const long i = (long)r * 96 + c;
        const float v = p0[i] + p1[i] + p2[i];
        y4[i] = v;
        s += v;
        q += v * v;
    }
    psum[(long)blockIdx.x * 96 + c] = s;
    psq [(long)blockIdx.x * 96 + c] = q;

    __threadfence();
    __syncthreads();
    if (c == 0) {
        int old = atomicAdd(ctr, 1);
        sLast = (old == (int)gridDim.x - 1);
    }
    __syncthreads();
    if (sLast) {
        __threadfence();
        const int lane = c & 31, warp = c >> 5;
        for (int d = warp; d < 96; d += 3) {
            float ss = 0.f, qq = 0.f;
            for (int b = lane; b < (int)gridDim.x; b += 32) {
                ss += psum[(long)b * 96 + d];
                qq += psq [(long)b * 96 + d];
            }
#pragma unroll
            for (int off = 16; off > 0; off >>= 1) {
                ss += __shfl_down_sync(0xFFFFFFFFu, ss, off);
                qq += __shfl_down_sync(0xFFFFFFFFu, qq, off);
            }
            if (lane == 0) {
                const float mean = ss * invM;
                const float var  = qq * invM - mean * mean;
                const float sc   = gamma[d] * rsqrtf(var + EPS_);
                oscale[d] = sc;
                oshift[d] = beta[d] - mean * sc;
            }
        }
        __syncthreads();
        if (c == 0) *ctr = 0;
    }
}

// ---------------------------------------------------------------------------
// Stage A: CIN=3 (padded to 4), one thread per row, weights in SMEM.
// ---------------------------------------------------------------------------
__global__ void __launch_bounds__(256)
conv_stageA(const float4* __restrict__ x4,
            const int*   __restrict__ neigh,
            const float* __restrict__ W,
            float* __restrict__ yout,
            float* __restrict__ psum, float* __restrict__ psq,
            const float* __restrict__ gamma, const float* __restrict__ beta,
            float* __restrict__ oscale, float* __restrict__ oshift,
            float invM, int* __restrict__ ctr)
{
    __shared__ float sW[27 * 3 * 24];
    __shared__ int   sIdx[256 * 27];
    __shared__ float sRed[8][24][2];
    __shared__ int   sLast;

    const int tid = threadIdx.x;
    const int row = blockIdx.x * 256 + tid;

    for (int i = tid; i < 27 * 3 * 24; i += 256) sW[i] = W[i];
    {
        const long base = (long)blockIdx.x * 256 * 27;
        for (int i = tid; i < 256 * 27; i += 256) sIdx[i] = neigh[base + i];
    }
    __syncthreads();

    float acc[24];
#pragma unroll
    for (int j = 0; j < 24; j++) acc[j] = 0.f;

#pragma unroll 3
    for (int k = 0; k < 27; k++) {
        const int idx = sIdx[tid * 27 + k];
        float4 xv = x4[idx];
        const float v[3] = {xv.x, xv.y, xv.z};
#pragma unroll
        for (int c = 0; c < 3; c++) {
            const float* wrow = &sW[(k * 3 + c) * 24];
#pragma unroll
            for (int j = 0; j < 24; j += 4) {
                float4 w4 = *reinterpret_cast<const float4*>(wrow + j);
                acc[j+0] = fmaf(v[c], w4.x, acc[j+0]);
                acc[j+1] = fmaf(v[c], w4.y, acc[j+1]);
                acc[j+2] = fmaf(v[c], w4.z, acc[j+2]);
                acc[j+3] = fmaf(v[c], w4.w, acc[j+3]);
            }
        }
    }

#pragma unroll
    for (int j = 0; j < 24; j += 4)
        *reinterpret_cast<float4*>(&yout[(long)row * 24 + j]) =
            make_float4(acc[j], acc[j+1], acc[j+2], acc[j+3]);

    const int lane = tid & 31, warp = tid >> 5;
#pragma unroll
    for (int j = 0; j < 24; j++) {
        float s = acc[j];
        float q = acc[j] * acc[j];
#pragma unroll
        for (int off = 16; off > 0; off >>= 1) {
            s += __shfl_down_sync(0xFFFFFFFFu, s, off);
            q += __shfl_down_sync(0xFFFFFFFFu, q, off);
        }
        if (lane == 0) { sRed[warp][j][0] = s; sRed[warp][j][1] = q; }
    }
    __syncthreads();
    if (tid < 24) {
        float s = 0.f, q = 0.f;
#pragma unroll
        for (int w = 0; w < 8; w++) { s += sRed[w][tid][0]; q += sRed[w][tid][1]; }
        psum[(long)blockIdx.x * 24 + tid] = s;
        psq [(long)blockIdx.x * 24 + tid] = q;
    }

    __threadfence();
    __syncthreads();
    if (tid == 0) {
        int old = atomicAdd(ctr, 1);
        sLast = (old == (int)gridDim.x - 1);
    }
    __syncthreads();
    if (sLast) {
        __threadfence();
        const int nRB = gridDim.x;
        for (int d = warp; d < 24; d += 8) {
            float s = 0.f, q = 0.f;
            for (int b = lane; b < nRB; b += 32) {
                s += psum[(long)b * 24 + d];
                q += psq [(long)b * 24 + d];
            }
#pragma unroll
            for (int off = 16; off > 0; off >>= 1) {
                s += __shfl_down_sync(0xFFFFFFFFu, s, off);
                q += __shfl_down_sync(0xFFFFFFFFu, q, off);
            }
            if (lane == 0) {
                const float mean = s * invM;
                const float var  = q * invM - mean * mean;
                const float sc   = gamma[d] * rsqrtf(var + EPS_);
                oscale[d] = sc;
                oshift[d] = beta[d] - mean * sc;
            }
        }
        __syncthreads();
        if (tid == 0) *ctr = 0;
    }
}

__global__ void pad4_kernel(const float* __restrict__ d, float4* __restrict__ o)
{
    const int i = blockIdx.x * 256 + threadIdx.x;
    if (i < N0_)
        o[i] = make_float4(d[3*i], d[3*i+1], d[3*i+2], 0.f);
}

__global__ void final_norm(const float* __restrict__ y,
                           const float* __restrict__ scale,
                           const float* __restrict__ shift,
                           float* __restrict__ out, int total, int cout)
{
    const int i = blockIdx.x * 256 + threadIdx.x;
    if (i < total) {
        const int d = i % cout;
        out[i] = fmaxf(fmaf(y[i], scale[d], shift[d]), 0.f);
    }
}

// ---------------------------------------------------------------------------
extern "C" void kernel_launch(void* const* d_in, const int* in_sizes, int n_in,
                              void* d_out, int out_size)
{
    const float* data   = (const float*)d_in[0];
    const int*   neigh0 = (const int*)  d_in[1];
    const int*   child0 = (const int*)  d_in[2];
    const int*   neigh1 = (const int*)  d_in[3];
    const int*   child1 = (const int*)  d_in[4];
    const int*   neigh2 = (const int*)  d_in[5];
    const float* w0  = (const float*)d_in[6];
    const float* g0  = (const float*)d_in[7];
    const float* b0  = (const float*)d_in[8];
    const float* wd0 = (const float*)d_in[9];
    const float* gd0 = (const float*)d_in[10];
    const float* bd0 = (const float*)d_in[11];
    const float* w1  = (const float*)d_in[12];
    const float* g1  = (const float*)d_in[13];
    const float* b1  = (const float*)d_in[14];
    const float* wd1 = (const float*)d_in[15];
    const float* gd1 = (const float*)d_in[16];
    const float* bd1 = (const float*)d_in[17];
    const float* wp  = (const float*)d_in[18];
    const float* gp  = (const float*)d_in[19];
    const float* bp  = (const float*)d_in[20];

    float4 *x4; float *y0,*y1,*y2,*y3,*y4,*ye,*psum,*psq,*scl,*shf; int *ctrs;
    cudaGetSymbolAddress((void**)&x4,   g_data4);
    cudaGetSymbolAddress((void**)&y0,   g_y0);
    cudaGetSymbolAddress((void**)&y1,   g_y1);
    cudaGetSymbolAddress((void**)&y2,   g_y2);
    cudaGetSymbolAddress((void**)&y3,   g_y3);
    cudaGetSymbolAddress((void**)&y4,   g_y4);
    cudaGetSymbolAddress((void**)&ye,   g_ye);
    cudaGetSymbolAddress((void**)&psum, g_psum);
    cudaGetSymbolAddress((void**)&psq,  g_psq);
    cudaGetSymbolAddress((void**)&scl,  g_scale);
    cudaGetSymbolAddress((void**)&shf,  g_shift);
    cudaGetSymbolAddress((void**)&ctrs, g_ctrs);

    // 0: pad input rows to float4
    pad4_kernel<<<(N0_ + 255) / 256, 256>>>(data, x4);

    // 1 — Stage A: data4 x w0[27,3,24] -> y0 + BN0
    conv_stageA<<<N0_/256, 256>>>(x4, neigh0, w0, y0, psum, psq,
                                  g0, b0, scl, shf, 1.f / N0_, ctrs + 0);

    // 2 — Stage B: norm0(y0) x wd0[8,24,48] -> y1 + BN1
    conv_gemm<8, 8, 24, 48, 48, 64, 4, 192, true, true>
        <<<dim3(N1_/64, 1, 1), 192>>>(
        y0, child0, wd0, scl, shf, y1, psum, psq,
        gd0, bd0, scl + 96, shf + 96, 1.f / N1_, ctrs + 1);

    // 3 — Stage C: norm1(y1) x w1[27,48,48] -> y2 + BN2
    conv_gemm<27, 27, 48, 48, 48, 64, 4, 192, true, true>
        <<<dim3(N1_/64, 1, 1), 192>>>(
        y1, neigh1, w1, scl + 96, shf + 96, y2, psum, psq,
        g1, b1, scl + 192, shf + 192, 1.f / N1_, ctrs + 2);

    // 4 — Stage D: norm2(y2) x wd1[8,48,96] -> y3 + BN3
    conv_gemm<8, 8, 48, 96, 48, 32, 2, 192, true, true>
        <<<dim3(N2_/32, 2, 1), 192>>>(
        y2, child1, wd1, scl + 192, shf + 192, y3, psum, psq,
        gd1, bd1, scl + 288, shf + 288, 1.f / N2_, ctrs + 3);

    // 5 — Stage E conv (k-split x3): norm3(y3) x wp[27,96,96] -> ye partials
    conv_gemm<9, 27, 96, 96, 48, 32, 2, 192, true, false>
        <<<dim3(N2_/32, 2, 3), 192>>>(
        y3, neigh2, wp, scl + 288, shf + 288, ye, nullptr, nullptr,
        nullptr, nullptr, nullptr, nullptr, 0.f, nullptr);

    // 6 — combine partials -> y4 + BN4
    combineE<<<N2_/64, 96>>>(ye, ye + N2_*96, ye + 2*N2_*96, y4, psum, psq,
                             gp, bp, scl + 384, shf + 384, 1.f / N2_, ctrs + 5);

    // 7 — final BN + ReLU -> d_out [N2, 96]
    final_norm<<<(N2_ * 96 + 255) / 256, 256>>>(
        y4, scl + 384, shf + 384, (float*)d_out, N2_ * 96, 96);
}